// round 16
// baseline (speedup 1.0000x reference)
#include <cuda_runtime.h>
#include <cstdint>

#define BB   512      // batch
#define LL   512      // leaves
#define EE   128      // emb
#define OPS  5
#define NI   511      // internal nodes
#define RPC  4        // batch rows per CTA

typedef unsigned long long ull;

// scratch: all node embeddings [B][NI][E]  (~134 MB)
__device__ float g_nodes[(size_t)BB * NI * EE];

// ---------------- packed f32x2 helpers ----------------
__device__ __forceinline__ ull pack2(float lo, float hi) {
    ull r;
    asm("mov.b64 %0, {%1, %2};" : "=l"(r) : "f"(lo), "f"(hi));
    return r;
}
__device__ __forceinline__ void fma2(ull& d, ull a, ull b) {
    asm("fma.rn.f32x2 %0, %1, %2, %0;" : "+l"(d) : "l"(a), "l"(b));
}
__device__ __forceinline__ ull add2(ull a, ull b) {
    ull r;
    asm("add.rn.f32x2 %0, %1, %2;" : "=l"(r) : "l"(a), "l"(b));
    return r;
}
__device__ __forceinline__ float2 unpack2(ull v) {
    float2 f;
    asm("mov.b64 {%0, %1}, %2;" : "=f"(f.x), "=f"(f.y) : "l"(v));
    return f;
}

// ---------------- sequential recurrence (warp-specialized) ----------------
// 512 threads = 16 warps. Warps 0-7 CONSUMERS: y_j = W_l*cur + c_j (critical
// path). Warps 8-15 PRODUCERS: c_{j+2} = W_r*leaf_{j+2} + b into a 3-slot
// ring. One __syncthreads per step.
// Race-free staging schedule: at step j producers stage leaf ri[j+2] into
// leafbuf[j&1] BEFORE barrier j; compute at step j reads leafbuf[j&1] AFTER
// barrier j. The next write to that slot (staging j+2) is after barrier j+1,
// while the read finishes before barrier j+1 -> no overlap.
// Within each role-warp: 16 output cols x 2 K-halves; lane = 2*(n&15)+h.
// Thread (n,h) owns the 64 K-floats of interleaved chunks {2i+h} -> every
// LDS.128 covers 2 adjacent 16B lines per warp = conflict-free wavefront.
// Reduce = horizontal add + ONE shfl_xor(1); h==0 lane commits.
__global__ void __launch_bounds__(512, 1) recur_kernel(
    const float* __restrict__ emb,   // [B, L, E]
    const float* __restrict__ Ww,    // [2E, E]
    const float* __restrict__ Wb,    // [E]
    const int*   __restrict__ li,    // [NI]
    const int*   __restrict__ ri)    // [NI]
{
    __shared__ __align__(16) float cur[2][RPC][EE];      // double-buffered state
    __shared__ __align__(16) float leafbuf[2][RPC][EE];  // staged right leaves
    __shared__ __align__(16) float cring[3][RPC][EE];    // c ring (incl. bias)
    __shared__ int ridx[NI + 4];

    const int t    = threadIdx.x;
    const int wid  = t >> 5;
    const int lane = t & 31;
    const bool prod = (wid >= 8);
    const int wgrp = wid & 7;                // 0..7 within role
    const int n    = wgrp * 16 + (lane >> 1);
    const int h    = lane & 1;
    const int b0   = blockIdx.x * RPC;

    // Weight slice for this role: rows side*128 + {8i+4h .. +3}, col n. 64 regs.
    ull w2[32];
    {
        const int side = prod ? 128 : 0;
#pragma unroll
        for (int i = 0; i < 16; i++) {
            const int k = side + 8 * i + 4 * h;
            w2[2*i]   = pack2(Ww[(size_t)k * EE + n],       Ww[(size_t)(k + 1) * EE + n]);
            w2[2*i+1] = pack2(Ww[(size_t)(k + 2) * EE + n], Ww[(size_t)(k + 3) * EE + n]);
        }
    }
    const float biasv = Wb[n];   // producers fold bias into c

    // right-leaf indices (+4 dummies for prefetch overrun)
    for (int j = t; j < NI; j += 512) ridx[j] = ri[j];
    if (t == 0) { ridx[NI] = ri[0]; ridx[NI+1] = ri[0]; ridx[NI+2] = ri[0]; ridx[NI+3] = ri[0]; }

    // init cur[0] = leaf(left_idx[0]): all threads, 1 float
    {
        const int l0 = li[0];
        const int r = t >> 7, c = t & 127;
        cur[0][r][c] = emb[((size_t)(b0 + r) * LL + l0) * EE + c];
    }
    // warmup staging: leafbuf[0] <- leaf(ri[0]), leafbuf[1] <- leaf(ri[1])
    {
        const int b = t >> 8;               // 0 or 1
        const int p = (t & 255) * 2;
        const int r = p >> 7, c = p & 127;
        const float2 v = *(const float2*)&emb[((size_t)(b0 + r) * LL + ri[b]) * EE + c];
        leafbuf[b][r][c]     = v.x;
        leafbuf[b][r][c + 1] = v.y;
    }
    __syncthreads();

    // producer staging identity (2 floats per producer thread)
    const int pt   = t & 255;
    const int r_ld = pt >> 6;
    const int c_ld = (pt & 63) * 2;

    // 2-register prefetch rotation: lv[j&1] staged at step j, then reloaded
    // with leaf ri[j+4] (consumed again at step j+2 -> distance-2 pipeline).
    float2 lv[2];
    lv[0] = make_float2(0.f, 0.f);
    lv[1] = make_float2(0.f, 0.f);
    if (prod) {
        lv[0] = *(const float2*)&emb[((size_t)(b0 + r_ld) * LL + ridx[2]) * EE + c_ld];
        lv[1] = *(const float2*)&emb[((size_t)(b0 + r_ld) * LL + ridx[3]) * EE + c_ld];
        // warmup: produce c_0, c_1 from leafbuf[0], leafbuf[1]
#pragma unroll
        for (int wj = 0; wj < 2; wj++) {
#pragma unroll
            for (int r = 0; r < RPC; r++) {
                const ulonglong2* xs = (const ulonglong2*)leafbuf[wj][r];
                ull s0 = 0ull, s1 = 0ull;
#pragma unroll
                for (int i = 0; i < 16; i++) {
                    const ulonglong2 p = xs[2*i + h];
                    fma2(s0, p.x, w2[2*i]);
                    fma2(s1, p.y, w2[2*i+1]);
                }
                const float2 f = unpack2(add2(s0, s1));
                float u = f.x + f.y;
                u += __shfl_xor_sync(0xFFFFFFFFu, u, 1);
                if (h == 0) cring[wj][r][n] = u + biasv;
            }
        }
    }
    __syncthreads();   // warmup c_0/c_1 + leafbuf reads complete before loop staging

    int cs = 0;   // consumer ring slot = j % 3
    int ps = 2;   // producer ring slot = (j+2) % 3
    for (int j = 0; j < NI; j++) {
        const int rb = j & 1;
        const int wb = rb ^ 1;
        const int lb = j & 1;

        if (prod) {
            // stage leaf ri[j+2] (consumed THIS step, after the barrier),
            // then reload the staged register with leaf ri[j+4]
            leafbuf[lb][r_ld][c_ld]     = lv[lb].x;
            leafbuf[lb][r_ld][c_ld + 1] = lv[lb].y;
            const int rnext = ridx[j + 4];
            lv[lb] = *(const float2*)&emb[((size_t)(b0 + r_ld) * LL + rnext) * EE + c_ld];
        }
        __syncthreads();   // cur[rb], cring[cs], leafbuf[lb] all ready

        if (!prod) {
            // ---- consumer: y_j = W_l * cur + c_j ----
#pragma unroll
            for (int r = 0; r < RPC; r++) {
                const ulonglong2* xs = (const ulonglong2*)cur[rb][r];
                ull s0 = 0ull, s1 = 0ull;
#pragma unroll
                for (int i = 0; i < 16; i++) {
                    const ulonglong2 p = xs[2*i + h];
                    fma2(s0, p.x, w2[2*i]);
                    fma2(s1, p.y, w2[2*i+1]);
                }
                const float2 f = unpack2(add2(s0, s1));
                float u = f.x + f.y;
                u += __shfl_xor_sync(0xFFFFFFFFu, u, 1);
                if (h == 0) {
                    const float y = u + cring[cs][r][n];
                    cur[wb][r][n] = y;
                    g_nodes[((size_t)(b0 + r) * NI + j) * EE + n] = y;
                }
            }
        } else {
            // ---- producer: c_{j+2} = W_r * leaf_{j+2} + b ----
#pragma unroll
            for (int r = 0; r < RPC; r++) {
                const ulonglong2* xs = (const ulonglong2*)leafbuf[lb][r];
                ull s0 = 0ull, s1 = 0ull;
#pragma unroll
                for (int i = 0; i < 16; i++) {
                    const ulonglong2 p = xs[2*i + h];
                    fma2(s0, p.x, w2[2*i]);
                    fma2(s1, p.y, w2[2*i+1]);
                }
                const float2 f = unpack2(add2(s0, s1));
                float u = f.x + f.y;
                u += __shfl_xor_sync(0xFFFFFFFFu, u, 1);
                if (h == 0) cring[ps][r][n] = u + biasv;
            }
        }
        cs = (cs == 2) ? 0 : cs + 1;
        ps = (ps == 2) ? 0 : ps + 1;
    }
}

// ---------------- parallel projection: op = node @ G_w + G_b ----------------
// 4 nodes per warp (4 outstanding LDG.128 -> DRAM latency shared)
__global__ void __launch_bounds__(256) proj_kernel(
    const float* __restrict__ Gw,   // [E, OPS]
    const float* __restrict__ Gb,   // [OPS]
    float* __restrict__ out,        // [B, NI, OPS]
    int total_quads)
{
    __shared__ float gws[EE * OPS];
    __shared__ float gbs[OPS];
    const int t = threadIdx.x;
    for (int i = t; i < EE * OPS; i += blockDim.x) gws[i] = Gw[i];
    if (t < OPS) gbs[t] = Gb[t];
    __syncthreads();

    const int quad = blockIdx.x * (blockDim.x >> 5) + (t >> 5);
    if (quad >= total_quads) return;
    const int lane  = t & 31;
    const size_t n0 = (size_t)quad * 4;

    float4 x[4];
#pragma unroll
    for (int q = 0; q < 4; q++)
        x[q] = *(const float4*)&g_nodes[(n0 + q) * EE + lane * 4];
    const float* g = &gws[lane * 4 * OPS];

    float p[4][OPS];
#pragma unroll
    for (int q = 0; q < 4; q++)
#pragma unroll
        for (int o = 0; o < OPS; o++)
            p[q][o] = x[q].x * g[o] + x[q].y * g[OPS + o]
                    + x[q].z * g[2 * OPS + o] + x[q].w * g[3 * OPS + o];

#pragma unroll
    for (int off = 16; off; off >>= 1)
#pragma unroll
        for (int q = 0; q < 4; q++)
#pragma unroll
            for (int o = 0; o < OPS; o++)
                p[q][o] += __shfl_xor_sync(0xFFFFFFFFu, p[q][o], off);

    if (lane == 0) {
        float* op = out + n0 * OPS;
#pragma unroll
        for (int q = 0; q < 4; q++)
#pragma unroll
            for (int o = 0; o < OPS; o++)
                op[q * OPS + o] = p[q][o] + gbs[o];
    }
}

// ---------------- labels tail ----------------
// Labels land on device as int32 (JAX x64 disabled). mode 1: float cast.
// mode 2: widen to raw int64.
__global__ void tail_kernel(const int* __restrict__ labels, float* __restrict__ out, int mode)
{
    const int j = blockIdx.x * blockDim.x + threadIdx.x;
    if (j >= NI) return;
    const size_t base = (size_t)BB * NI * OPS;
    if (mode == 1) {
        out[base + j] = (float)labels[j];
    } else {
        ((long long*)(out + base))[j] = (long long)labels[j];
    }
}

extern "C" void kernel_launch(void* const* d_in, const int* in_sizes, int n_in,
                              void* d_out, int out_size)
{
    const float* emb    = (const float*)d_in[0];
    const float* Ww     = (const float*)d_in[1];
    const float* Wb     = (const float*)d_in[2];
    const float* Gw     = (const float*)d_in[3];
    const float* Gb     = (const float*)d_in[4];
    const int*   li     = (const int*)d_in[5];
    const int*   ri     = (const int*)d_in[6];
    const int*   labels = (const int*)d_in[7];
    float*       out    = (float*)d_out;

    recur_kernel<<<BB / RPC, 512>>>(emb, Ww, Wb, li, ri);

    const int total_quads = BB * NI / 4;                   // 65408
    proj_kernel<<<total_quads / 8, 256>>>(Gw, Gb, out, total_quads); // 8 warps/block

    const long long base = (long long)BB * NI * OPS;
    const long long tail = (long long)out_size - base;
    if (tail == NI)          tail_kernel<<<2, 256>>>(labels, out, 1);
    else if (tail == 2 * NI) tail_kernel<<<2, 256>>>(labels, out, 2);
}

// round 17
// speedup vs baseline: 1.2617x; 1.2617x over previous
#include <cuda_runtime.h>
#include <cstdint>

#define BB   512      // batch
#define LL   512      // leaves
#define EE   128      // emb
#define OPS  5
#define NI   511      // internal nodes
#define RPC  4        // batch rows per CTA

typedef unsigned long long ull;

// scratch: all node embeddings [B][NI][E]  (~134 MB)
__device__ float g_nodes[(size_t)BB * NI * EE];

// ---------------- packed f32x2 helpers ----------------
__device__ __forceinline__ ull pack2(float lo, float hi) {
    ull r;
    asm("mov.b64 %0, {%1, %2};" : "=l"(r) : "f"(lo), "f"(hi));
    return r;
}
__device__ __forceinline__ void fma2(ull& d, ull a, ull b) {
    asm("fma.rn.f32x2 %0, %1, %2, %0;" : "+l"(d) : "l"(a), "l"(b));
}
__device__ __forceinline__ ull add2(ull a, ull b) {
    ull r;
    asm("add.rn.f32x2 %0, %1, %2;" : "=l"(r) : "l"(a), "l"(b));
    return r;
}
__device__ __forceinline__ float2 unpack2(ull v) {
    float2 f;
    asm("mov.b64 {%0, %1}, %2;" : "=f"(f.x), "=f"(f.y) : "l"(v));
    return f;
}
#define BAR_ALL()  asm volatile("bar.sync 0, 512;" ::: "memory")
#define BAR_CUR()  asm volatile("bar.sync 1, 256;" ::: "memory")
#define BAR_LEAF() asm volatile("bar.sync 2, 256;" ::: "memory")

// dynamic-smem layout
struct RS {
    float cur[2][RPC][EE];          // 4 KB  double-buffered state
    float leafbuf[2][RPC][EE];      // 4 KB  staged right leaves
    float red_cur[8][RPC][EE];      // 16 KB cur-side partials
    float red_leaf[2][8][RPC][EE];  // 32 KB leaf-side partials (double-buffered)
    int   ridx[NI + 4];
};

// ---------------- sequential recurrence (decoupled barrier groups) --------
// 512 threads = 16 warps, R14 broadcast layout. Warps 0-7 (CUR group) own
// 16-float K-slices of cur (W_l); warps 8-15 (LEAF group) own 16-float
// K-slices of leaf (W_r). Lane l owns cols {l, l+32, l+64, l+96}; all 32
// lanes read the SAME 16B x-chunk -> broadcast = 1 wavefront per LDS.128.
// Barrier graph per step j:
//   CUR:  phaseA(j) -> bar0(512) -> phaseB(j) [sum 16 partials + bias,
//         commit cur[(j+1)&1] + g_nodes] -> bar1(256)
//   LEAF: phaseA(j) [writes red_leaf[j&1]] -> bar0(512) -> stage leaf j+1
//         (distance-2 LDG rotation) -> bar2(256)
// LEAF's phaseA(j+1) overlaps CUR's phaseB(j), keeping the fma pipe fed.
// Races: red_leaf slot rewritten at phaseA(j+2), which is after bar0(j+1),
// which requires CUR arrival post-phaseB(j) (the read). All other buffers
// are single-group and ordered by their group barrier.
__global__ void __launch_bounds__(512, 1) recur_kernel(
    const float* __restrict__ emb,   // [B, L, E]
    const float* __restrict__ Ww,    // [2E, E]
    const float* __restrict__ Wb,    // [E]
    const int*   __restrict__ li,    // [NI]
    const int*   __restrict__ ri)    // [NI]
{
    extern __shared__ char smraw[];
    RS* sm = (RS*)smraw;

    const int t    = threadIdx.x;
    const int wid  = t >> 5;
    const int lane = t & 31;
    const int b0   = blockIdx.x * RPC;
    const bool isleaf = (wid >= 8);
    const int ws   = wid & 7;       // slice index within group

    // Weight slice: Ww rows side*128 + 16*ws .. +15, cols lane+32c. 32 b64.
    ull w[4][8];
    {
        const int side = isleaf ? 128 : 0;
#pragma unroll
        for (int c = 0; c < 4; c++) {
            const int n = lane + 32 * c;
#pragma unroll
            for (int i = 0; i < 8; i++) {
                const int k = side + 16 * ws + 2 * i;
                w[c][i] = pack2(Ww[(size_t)k * EE + n], Ww[(size_t)(k + 1) * EE + n]);
            }
        }
    }

    // right-leaf indices (+4 dummies)
    for (int j = t; j < NI; j += 512) sm->ridx[j] = ri[j];
    if (t == 0) {
        sm->ridx[NI] = ri[0]; sm->ridx[NI+1] = ri[0];
        sm->ridx[NI+2] = ri[0]; sm->ridx[NI+3] = ri[0];
    }

    // ---------------- pre-loop staging ----------------
    float2 lv[2];
    lv[0] = make_float2(0.f, 0.f);
    lv[1] = make_float2(0.f, 0.f);
    const int pt   = t & 255;
    const int r_ld = pt >> 6;
    const int c_ld = (pt & 63) * 2;
    if (!isleaf) {
        // cur[0] = leaf(left_idx[0]); 256 threads x 2 floats
        const int l0 = li[0];
        const float2 v = *(const float2*)&emb[((size_t)(b0 + r_ld) * LL + l0) * EE + c_ld];
        sm->cur[0][r_ld][c_ld]     = v.x;
        sm->cur[0][r_ld][c_ld + 1] = v.y;
    } else {
        // leafbuf[0] = leaf(ri[0]); prefetch ri[1] (lv[1]), ri[2] (lv[0])
        const float2 v = *(const float2*)&emb[((size_t)(b0 + r_ld) * LL + ri[0]) * EE + c_ld];
        sm->leafbuf[0][r_ld][c_ld]     = v.x;
        sm->leafbuf[0][r_ld][c_ld + 1] = v.y;
        lv[1] = *(const float2*)&emb[((size_t)(b0 + r_ld) * LL + ri[1]) * EE + c_ld];
        lv[0] = *(const float2*)&emb[((size_t)(b0 + r_ld) * LL + ri[2]) * EE + c_ld];
    }
    __syncthreads();

    if (!isleaf) {
        // ================= CUR group =================
        const ulonglong2* xb0 = (const ulonglong2*)sm->cur + ws * 4;
        const ulonglong2* xb1 = xb0 + RPC * 32;
        const int  col   = t & 127;
        const int  row1  = t >> 7;          // 0..1 ; commits rows row1, row1+2
        const float biasv = Wb[col];

        for (int j = 0; j < NI; j++) {
            const int rb = j & 1;
            const ulonglong2* xb = rb ? xb1 : xb0;

            // ---- phase A: cur-side partials ----
#pragma unroll
            for (int r = 0; r < RPC; r++) {
                const ulonglong2* xs = xb + r * 32;
                ull a0[4] = {0,0,0,0}, a1[4] = {0,0,0,0};
#pragma unroll
                for (int jj = 0; jj < 4; jj++) {
                    const ulonglong2 p = xs[jj];
#pragma unroll
                    for (int c = 0; c < 4; c++) {
                        fma2(a0[c], p.x, w[c][2*jj]);
                        fma2(a1[c], p.y, w[c][2*jj+1]);
                    }
                }
#pragma unroll
                for (int c = 0; c < 4; c++) {
                    const float2 f = unpack2(add2(a0[c], a1[c]));
                    sm->red_cur[ws][r][lane + 32 * c] = f.x + f.y;
                }
            }
            BAR_ALL();      // all 16 partial sets for step j ready

            // ---- phase B: two commits per thread ----
            const float* rl = &sm->red_leaf[rb][0][0][0];
#pragma unroll
            for (int o = 0; o < 2; o++) {
                const int row = row1 + 2 * o;
                float v[16];
#pragma unroll
                for (int sl = 0; sl < 8; sl++)
                    v[sl] = sm->red_cur[sl][row][col];
#pragma unroll
                for (int sl = 0; sl < 8; sl++)
                    v[8 + sl] = rl[(sl * RPC + row) * EE + col];
                float s01 = v[0]+v[1],   s23 = v[2]+v[3];
                float s45 = v[4]+v[5],   s67 = v[6]+v[7];
                float s89 = v[8]+v[9],   sab = v[10]+v[11];
                float scd = v[12]+v[13], sef = v[14]+v[15];
                const float y = ((s01+s23)+(s45+s67)) + ((s89+sab)+(scd+sef)) + biasv;
                sm->cur[rb ^ 1][row][col] = y;
                g_nodes[((size_t)(b0 + row) * NI + j) * EE + col] = y;
            }
            BAR_CUR();      // cur[(j+1)&1] ready for cur-group phase A(j+1)
        }
    } else {
        // ================= LEAF group =================
        const ulonglong2* lb0 = (const ulonglong2*)sm->leafbuf + ws * 4;
        const ulonglong2* lb1 = lb0 + RPC * 32;

        for (int j = 0; j < NI; j++) {
            const int lb = j & 1;
            const ulonglong2* xb = lb ? lb1 : lb0;

            // ---- phase A: leaf-side partials for step j ----
#pragma unroll
            for (int r = 0; r < RPC; r++) {
                const ulonglong2* xs = xb + r * 32;
                ull a0[4] = {0,0,0,0}, a1[4] = {0,0,0,0};
#pragma unroll
                for (int jj = 0; jj < 4; jj++) {
                    const ulonglong2 p = xs[jj];
#pragma unroll
                    for (int c = 0; c < 4; c++) {
                        fma2(a0[c], p.x, w[c][2*jj]);
                        fma2(a1[c], p.y, w[c][2*jj+1]);
                    }
                }
#pragma unroll
                for (int c = 0; c < 4; c++) {
                    const float2 f = unpack2(add2(a0[c], a1[c]));
                    sm->red_leaf[lb][ws][r][lane + 32 * c] = f.x + f.y;
                }
            }
            BAR_ALL();      // partials published for phase B(j)

            // ---- stage leaf ri[j+1] into slot (j+1)&1, reload register ----
            const int nlb = lb ^ 1;
            sm->leafbuf[nlb][r_ld][c_ld]     = lv[nlb].x;
            sm->leafbuf[nlb][r_ld][c_ld + 1] = lv[nlb].y;
            const int rnext = sm->ridx[j + 3];
            lv[nlb] = *(const float2*)&emb[((size_t)(b0 + r_ld) * LL + rnext) * EE + c_ld];
            BAR_LEAF();     // leafbuf[(j+1)&1] ready for leaf phase A(j+1)
        }
    }
}

// ---------------- parallel projection: op = node @ G_w + G_b ----------------
// 4 nodes per warp (4 outstanding LDG.128 -> DRAM latency shared)
__global__ void __launch_bounds__(256) proj_kernel(
    const float* __restrict__ Gw,   // [E, OPS]
    const float* __restrict__ Gb,   // [OPS]
    float* __restrict__ out,        // [B, NI, OPS]
    int total_quads)
{
    __shared__ float gws[EE * OPS];
    __shared__ float gbs[OPS];
    const int t = threadIdx.x;
    for (int i = t; i < EE * OPS; i += blockDim.x) gws[i] = Gw[i];
    if (t < OPS) gbs[t] = Gb[t];
    __syncthreads();

    const int quad = blockIdx.x * (blockDim.x >> 5) + (t >> 5);
    if (quad >= total_quads) return;
    const int lane  = t & 31;
    const size_t n0 = (size_t)quad * 4;

    float4 x[4];
#pragma unroll
    for (int q = 0; q < 4; q++)
        x[q] = *(const float4*)&g_nodes[(n0 + q) * EE + lane * 4];
    const float* g = &gws[lane * 4 * OPS];

    float p[4][OPS];
#pragma unroll
    for (int q = 0; q < 4; q++)
#pragma unroll
        for (int o = 0; o < OPS; o++)
            p[q][o] = x[q].x * g[o] + x[q].y * g[OPS + o]
                    + x[q].z * g[2 * OPS + o] + x[q].w * g[3 * OPS + o];

#pragma unroll
    for (int off = 16; off; off >>= 1)
#pragma unroll
        for (int q = 0; q < 4; q++)
#pragma unroll
            for (int o = 0; o < OPS; o++)
                p[q][o] += __shfl_xor_sync(0xFFFFFFFFu, p[q][o], off);

    if (lane == 0) {
        float* op = out + n0 * OPS;
#pragma unroll
        for (int q = 0; q < 4; q++)
#pragma unroll
            for (int o = 0; o < OPS; o++)
                op[q * OPS + o] = p[q][o] + gbs[o];
    }
}

// ---------------- labels tail ----------------
// Labels land on device as int32 (JAX x64 disabled). mode 1: float cast.
// mode 2: widen to raw int64.
__global__ void tail_kernel(const int* __restrict__ labels, float* __restrict__ out, int mode)
{
    const int j = blockIdx.x * blockDim.x + threadIdx.x;
    if (j >= NI) return;
    const size_t base = (size_t)BB * NI * OPS;
    if (mode == 1) {
        out[base + j] = (float)labels[j];
    } else {
        ((long long*)(out + base))[j] = (long long)labels[j];
    }
}

extern "C" void kernel_launch(void* const* d_in, const int* in_sizes, int n_in,
                              void* d_out, int out_size)
{
    const float* emb    = (const float*)d_in[0];
    const float* Ww     = (const float*)d_in[1];
    const float* Wb     = (const float*)d_in[2];
    const float* Gw     = (const float*)d_in[3];
    const float* Gb     = (const float*)d_in[4];
    const int*   li     = (const int*)d_in[5];
    const int*   ri     = (const int*)d_in[6];
    const int*   labels = (const int*)d_in[7];
    float*       out    = (float*)d_out;

    const int smem_bytes = (int)sizeof(RS);
    cudaFuncSetAttribute(recur_kernel,
                         cudaFuncAttributeMaxDynamicSharedMemorySize, smem_bytes);

    recur_kernel<<<BB / RPC, 512, smem_bytes>>>(emb, Ww, Wb, li, ri);

    const int total_quads = BB * NI / 4;                   // 65408
    proj_kernel<<<total_quads / 8, 256>>>(Gw, Gb, out, total_quads); // 8 warps/block

    const long long base = (long long)BB * NI * OPS;
    const long long tail = (long long)out_size - base;
    if (tail == NI)          tail_kernel<<<2, 256>>>(labels, out, 1);
    else if (tail == 2 * NI) tail_kernel<<<2, 256>>>(labels, out, 2);
}